// round 7
// baseline (speedup 1.0000x reference)
#include <cuda_runtime.h>
#include <cuda_bf16.h>
#include <math.h>
#include <stdint.h>

// LatticeMaxPooling (quincunx):
//   out0[i,j] = max(c0[i,j], c1[i,j], c0[i+1,j], c0[i,j+1], c0[i+1,j+1])
//   out1[i,j] = max(c1[i,j], c0[i+1,j+1], c1[i+1,j], c1[i,j+1], c1[i+1,j+1])
// [B=4, C=32, H=512, W=512] f32 per coset; output [2,B,C,H,W].
// DRAM-bound at the ~512 MiB traffic floor. R6: 80.4us @ 81% DRAM.
// This version: 2 output rows per thread (shares the middle input row),
// streaming stores, shuffle-based j+1 shifts (lane 31 loads the tail).

#define QP_W 512
#define QP_VPR 128            // vec4 slots per row
#define QP_THREADS 256

__device__ __forceinline__ float qp_max5(float a, float b, float c, float d, float e) {
    return fmaxf(fmaxf(fmaxf(a, b), fmaxf(c, d)), e);
}

__global__ __launch_bounds__(QP_THREADS)
void LatticeMaxPooling_pair_kernel(
    const float* __restrict__ c0,
    const float* __restrict__ c1,
    float* __restrict__ out,
    int n_pairs,      // row pairs = B*C*H/2
    int H,            // rows per image (power of two, even)
    int total)        // elements per coset (fits int32)
{
    const float NEGINF = -INFINITY;
    const int n_work = n_pairs * QP_VPR;
    const int stride = gridDim.x * blockDim.x;
    const int hmask = H - 1;
    const bool last_lane = ((threadIdx.x & 31) == 31);

    for (int idx = blockIdx.x * blockDim.x + threadIdx.x; idx < n_work; idx += stride) {
        const int p     = idx >> 7;               // row-pair index
        const int t     = idx & (QP_VPR - 1);
        const int r0    = p * 2;                  // first output row
        const int i0    = r0 & hmask;             // even; i0+1 < H always
        const int base0 = r0 * QP_W;
        const bool has2 = (i0 + 2 < H);           // row r0+2 in-image?
        const bool has_e = (t != QP_VPR - 1);

        // 6 vec4 loads: rows r0, r0+1, r0+2 of both cosets.
        float4 a0 = reinterpret_cast<const float4*>(c0 + base0)[t];
        float4 b0 = reinterpret_cast<const float4*>(c1 + base0)[t];
        float4 a1 = reinterpret_cast<const float4*>(c0 + base0 + QP_W)[t];
        float4 b1 = reinterpret_cast<const float4*>(c1 + base0 + QP_W)[t];
        float4 a2, b2;
        if (has2) {
            a2 = reinterpret_cast<const float4*>(c0 + base0 + 2 * QP_W)[t];
            b2 = reinterpret_cast<const float4*>(c1 + base0 + 2 * QP_W)[t];
        } else {
            a2 = make_float4(NEGINF, NEGINF, NEGINF, NEGINF);
            b2 = a2;
        }

        // Warp-boundary tail (j0+4): lane 31 loads, others shuffle from lane+1.
        float a0e_l = NEGINF, b0e_l = NEGINF, a1e_l = NEGINF,
              b1e_l = NEGINF, a2e_l = NEGINF, b2e_l = NEGINF;
        if (last_lane && has_e) {
            const int e = base0 + t * 4 + 4;
            a0e_l = c0[e];
            b0e_l = c1[e];
            a1e_l = c0[e + QP_W];
            b1e_l = c1[e + QP_W];
            if (has2) {
                a2e_l = c0[e + 2 * QP_W];
                b2e_l = c1[e + 2 * QP_W];
            }
        }
        float a0e = __shfl_down_sync(0xFFFFFFFFu, a0.x, 1);
        float b0e = __shfl_down_sync(0xFFFFFFFFu, b0.x, 1);
        float a1e = __shfl_down_sync(0xFFFFFFFFu, a1.x, 1);
        float b1e = __shfl_down_sync(0xFFFFFFFFu, b1.x, 1);
        float a2e = __shfl_down_sync(0xFFFFFFFFu, a2.x, 1);
        float b2e = __shfl_down_sync(0xFFFFFFFFu, b2.x, 1);
        if (last_lane) {
            a0e = a0e_l; b0e = b0e_l; a1e = a1e_l;
            b1e = b1e_l; a2e = a2e_l; b2e = b2e_l;
        }

        // j+1 shifted views
        const float4 sa0 = make_float4(a0.y, a0.z, a0.w, a0e);
        const float4 sa1 = make_float4(a1.y, a1.z, a1.w, a1e);
        const float4 sa2 = make_float4(a2.y, a2.z, a2.w, a2e);
        const float4 sb0 = make_float4(b0.y, b0.z, b0.w, b0e);
        const float4 sb1 = make_float4(b1.y, b1.z, b1.w, b1e);
        const float4 sb2 = make_float4(b2.y, b2.z, b2.w, b2e);

        float4 o00, o10, o01, o11;
        // Row r0
        o00.x = qp_max5(a0.x, b0.x, a1.x, sa0.x, sa1.x);
        o00.y = qp_max5(a0.y, b0.y, a1.y, sa0.y, sa1.y);
        o00.z = qp_max5(a0.z, b0.z, a1.z, sa0.z, sa1.z);
        o00.w = qp_max5(a0.w, b0.w, a1.w, sa0.w, sa1.w);
        o10.x = qp_max5(b0.x, sa1.x, b1.x, sb0.x, sb1.x);
        o10.y = qp_max5(b0.y, sa1.y, b1.y, sb0.y, sb1.y);
        o10.z = qp_max5(b0.z, sa1.z, b1.z, sb0.z, sb1.z);
        o10.w = qp_max5(b0.w, sa1.w, b1.w, sb0.w, sb1.w);
        // Row r0+1
        o01.x = qp_max5(a1.x, b1.x, a2.x, sa1.x, sa2.x);
        o01.y = qp_max5(a1.y, b1.y, a2.y, sa1.y, sa2.y);
        o01.z = qp_max5(a1.z, b1.z, a2.z, sa1.z, sa2.z);
        o01.w = qp_max5(a1.w, b1.w, a2.w, sa1.w, sa2.w);
        o11.x = qp_max5(b1.x, sa2.x, b2.x, sb1.x, sb2.x);
        o11.y = qp_max5(b1.y, sa2.y, b2.y, sb1.y, sb2.y);
        o11.z = qp_max5(b1.z, sa2.z, b2.z, sb1.z, sb2.z);
        o11.w = qp_max5(b1.w, sa2.w, b2.w, sb1.w, sb2.w);

        // Streaming stores (outputs are never re-read).
        float4* o0p  = reinterpret_cast<float4*>(out + base0) + t;
        float4* o0p1 = reinterpret_cast<float4*>(out + base0 + QP_W) + t;
        float4* o1p  = reinterpret_cast<float4*>(out + total + base0) + t;
        float4* o1p1 = reinterpret_cast<float4*>(out + total + base0 + QP_W) + t;
        __stcs(o0p,  o00);
        __stcs(o0p1, o01);
        __stcs(o1p,  o10);
        __stcs(o1p1, o11);
    }
}

// Fallback (unaligned pointers / odd sizes): scalar path. Not expected to run.
__global__ __launch_bounds__(QP_THREADS)
void LatticeMaxPooling_scalar_kernel(
    const float* __restrict__ c0,
    const float* __restrict__ c1,
    float* __restrict__ out,
    long long n_rows, int H, long long total)
{
    const float NEGINF = -INFINITY;
    const long long n_work = n_rows * QP_W;
    const long long stride = (long long)gridDim.x * blockDim.x;
    for (long long idx = (long long)blockIdx.x * blockDim.x + threadIdx.x;
         idx < n_work; idx += stride) {
        const long long row = idx / QP_W;
        const int j = (int)(idx - row * QP_W);
        const int i = (int)(row % H);
        const long long base = row * QP_W;
        const bool he = (j + 1 < QP_W);
        const bool hn = (i + 1 < H);

        float a00 = c0[base + j];
        float b00 = c1[base + j];
        float a01 = he ? c0[base + j + 1] : NEGINF;
        float b01 = he ? c1[base + j + 1] : NEGINF;
        float a10 = hn ? c0[base + QP_W + j] : NEGINF;
        float b10 = hn ? c1[base + QP_W + j] : NEGINF;
        float a11 = (hn && he) ? c0[base + QP_W + j + 1] : NEGINF;
        float b11 = (hn && he) ? c1[base + QP_W + j + 1] : NEGINF;

        out[base + j]         = qp_max5(a00, b00, a10, a01, a11);
        out[total + base + j] = qp_max5(b00, a11, b10, b01, b11);
    }
}

extern "C" void kernel_launch(void* const* d_in, const int* in_sizes, int n_in,
                              void* d_out, int out_size) {
    const float* c0 = (const float*)d_in[0];
    const float* c1 = (const float*)d_in[1];
    float* out = (float*)d_out;

    long long t_in  = (long long)in_sizes[0];
    long long t_out = (long long)out_size / 2;
    long long total = (t_in < t_out) ? t_in : t_out;

    const int H = 512;
    const long long n_rows = total / QP_W;
    total = n_rows * QP_W;

    const bool fast =
        ((uintptr_t)c0 % 16 == 0) && ((uintptr_t)c1 % 16 == 0) &&
        ((uintptr_t)out % 16 == 0) &&
        ((n_rows % 2) == 0) &&
        (2 * total < 0x7FFFFFFFLL);           // int32-indexable

    if (fast) {
        const int n_pairs = (int)(n_rows / 2);
        const int n_work = n_pairs * QP_VPR;
        int blocks = (n_work + QP_THREADS - 1) / QP_THREADS;
        if (blocks < 1) blocks = 1;
        LatticeMaxPooling_pair_kernel<<<blocks, QP_THREADS>>>(
            c0, c1, out, n_pairs, H, (int)total);
    } else {
        const long long n_work = n_rows * QP_W;
        int blocks = (int)((n_work + QP_THREADS - 1) / QP_THREADS);
        if (blocks < 1) blocks = 1;
        LatticeMaxPooling_scalar_kernel<<<blocks, QP_THREADS>>>(
            c0, c1, out, n_rows, H, total);
    }
}

// round 8
// speedup vs baseline: 1.0004x; 1.0004x over previous
#include <cuda_runtime.h>
#include <cuda_bf16.h>
#include <math.h>
#include <stdint.h>

// LatticeMaxPooling (quincunx):
//   out0[i,j] = max(c0[i,j], c1[i,j], c0[i+1,j], c0[i,j+1], c0[i+1,j+1])
//   out1[i,j] = max(c1[i,j], c0[i+1,j+1], c1[i+1,j], c1[i,j+1], c1[i+1,j+1])
// [B=4, C=32, H=512, W=512] f32 per coset; output [2,B,C,H,W].
// DRAM-bound at the ~537 MB traffic floor; measured ceiling ~6.46 TB/s.
// R8 = R6 winner (1 row/thread, shuffle shifts) + streaming stores only.

#define QP_W 512
#define QP_VPR 128            // vec4 slots per row
#define QP_THREADS 256

__device__ __forceinline__ float qp_max5(float a, float b, float c, float d, float e) {
    return fmaxf(fmaxf(fmaxf(a, b), fmaxf(c, d)), e);
}

__global__ __launch_bounds__(QP_THREADS)
void LatticeMaxPooling_vec_kernel(
    const float* __restrict__ c0,
    const float* __restrict__ c1,
    float* __restrict__ out,
    int n_rows,       // total rows = B*C*H
    int H,            // rows per image (power of two)
    int total)        // elements per coset (fits int32)
{
    const float NEGINF = -INFINITY;
    const int n_work = n_rows * QP_VPR;
    const int stride = gridDim.x * blockDim.x;
    const int hmask = H - 1;
    const bool last_lane = ((threadIdx.x & 31) == 31);

    for (int idx = blockIdx.x * blockDim.x + threadIdx.x; idx < n_work; idx += stride) {
        const int row  = idx >> 7;                // / QP_VPR
        const int t    = idx & (QP_VPR - 1);
        const int i    = row & hmask;
        const int base = row * QP_W;
        const bool has_n = (i + 1 < H);
        const bool has_e = (t != QP_VPR - 1);     // j0+4 < 512

        // Vector loads: row i and i+1 of both cosets.
        float4 a0 = reinterpret_cast<const float4*>(c0 + base)[t];
        float4 b0 = reinterpret_cast<const float4*>(c1 + base)[t];
        float4 a1, b1;
        if (has_n) {
            a1 = reinterpret_cast<const float4*>(c0 + base + QP_W)[t];
            b1 = reinterpret_cast<const float4*>(c1 + base + QP_W)[t];
        } else {
            a1 = make_float4(NEGINF, NEGINF, NEGINF, NEGINF);
            b1 = a1;
        }

        // Warp-boundary element (j0+4): lane 31 loads, others shuffle from lane+1.
        float a0e_l = NEGINF, b0e_l = NEGINF, a1e_l = NEGINF, b1e_l = NEGINF;
        if (last_lane && has_e) {
            const int e = base + t * 4 + 4;
            a0e_l = c0[e];
            b0e_l = c1[e];
            if (has_n) {
                a1e_l = c0[e + QP_W];
                b1e_l = c1[e + QP_W];
            }
        }
        float a0e = __shfl_down_sync(0xFFFFFFFFu, a0.x, 1);
        float b0e = __shfl_down_sync(0xFFFFFFFFu, b0.x, 1);
        float a1e = __shfl_down_sync(0xFFFFFFFFu, a1.x, 1);
        float b1e = __shfl_down_sync(0xFFFFFFFFu, b1.x, 1);
        if (last_lane) { a0e = a0e_l; b0e = b0e_l; a1e = a1e_l; b1e = b1e_l; }

        // j+1 shifted views
        const float4 sa0 = make_float4(a0.y, a0.z, a0.w, a0e);
        const float4 sa1 = make_float4(a1.y, a1.z, a1.w, a1e);
        const float4 sb0 = make_float4(b0.y, b0.z, b0.w, b0e);
        const float4 sb1 = make_float4(b1.y, b1.z, b1.w, b1e);

        float4 o0, o1;
        o0.x = qp_max5(a0.x, b0.x, a1.x, sa0.x, sa1.x);
        o0.y = qp_max5(a0.y, b0.y, a1.y, sa0.y, sa1.y);
        o0.z = qp_max5(a0.z, b0.z, a1.z, sa0.z, sa1.z);
        o0.w = qp_max5(a0.w, b0.w, a1.w, sa0.w, sa1.w);

        o1.x = qp_max5(b0.x, sa1.x, b1.x, sb0.x, sb1.x);
        o1.y = qp_max5(b0.y, sa1.y, b1.y, sb0.y, sb1.y);
        o1.z = qp_max5(b0.z, sa1.z, b1.z, sb0.z, sb1.z);
        o1.w = qp_max5(b0.w, sa1.w, b1.w, sb0.w, sb1.w);

        // Streaming stores: outputs are never re-read; keep L2 for input rows.
        __stcs(reinterpret_cast<float4*>(out + base) + t,         o0);
        __stcs(reinterpret_cast<float4*>(out + total + base) + t, o1);
    }
}

// Fallback (unaligned pointers / odd sizes): scalar path. Not expected to run.
__global__ __launch_bounds__(QP_THREADS)
void LatticeMaxPooling_scalar_kernel(
    const float* __restrict__ c0,
    const float* __restrict__ c1,
    float* __restrict__ out,
    long long n_rows, int H, long long total)
{
    const float NEGINF = -INFINITY;
    const long long n_work = n_rows * QP_W;
    const long long stride = (long long)gridDim.x * blockDim.x;
    for (long long idx = (long long)blockIdx.x * blockDim.x + threadIdx.x;
         idx < n_work; idx += stride) {
        const long long row = idx / QP_W;
        const int j = (int)(idx - row * QP_W);
        const int i = (int)(row % H);
        const long long base = row * QP_W;
        const bool he = (j + 1 < QP_W);
        const bool hn = (i + 1 < H);

        float a00 = c0[base + j];
        float b00 = c1[base + j];
        float a01 = he ? c0[base + j + 1] : NEGINF;
        float b01 = he ? c1[base + j + 1] : NEGINF;
        float a10 = hn ? c0[base + QP_W + j] : NEGINF;
        float b10 = hn ? c1[base + QP_W + j] : NEGINF;
        float a11 = (hn && he) ? c0[base + QP_W + j + 1] : NEGINF;
        float b11 = (hn && he) ? c1[base + QP_W + j + 1] : NEGINF;

        out[base + j]         = qp_max5(a00, b00, a10, a01, a11);
        out[total + base + j] = qp_max5(b00, a11, b10, b01, b11);
    }
}

extern "C" void kernel_launch(void* const* d_in, const int* in_sizes, int n_in,
                              void* d_out, int out_size) {
    const float* c0 = (const float*)d_in[0];
    const float* c1 = (const float*)d_in[1];
    float* out = (float*)d_out;

    long long t_in  = (long long)in_sizes[0];
    long long t_out = (long long)out_size / 2;
    long long total = (t_in < t_out) ? t_in : t_out;

    const int H = 512;
    const long long n_rows = total / QP_W;
    total = n_rows * QP_W;

    const bool fast =
        ((uintptr_t)c0 % 16 == 0) && ((uintptr_t)c1 % 16 == 0) &&
        ((uintptr_t)out % 16 == 0) &&
        (2 * total < 0x7FFFFFFFLL);           // int32-indexable

    if (fast) {
        const int n_work = (int)(n_rows * QP_VPR);
        int blocks = (n_work + QP_THREADS - 1) / QP_THREADS;
        if (blocks < 1) blocks = 1;
        LatticeMaxPooling_vec_kernel<<<blocks, QP_THREADS>>>(
            c0, c1, out, (int)n_rows, H, (int)total);
    } else {
        const long long n_work = n_rows * QP_W;
        int blocks = (int)((n_work + QP_THREADS - 1) / QP_THREADS);
        if (blocks < 1) blocks = 1;
        LatticeMaxPooling_scalar_kernel<<<blocks, QP_THREADS>>>(
            c0, c1, out, n_rows, H, total);
    }
}

// round 11
// speedup vs baseline: 1.0008x; 1.0004x over previous
#include <cuda_runtime.h>
#include <cuda_bf16.h>
#include <math.h>
#include <stdint.h>

// LatticeMaxPooling (quincunx):
//   out0[i,j] = max(c0[i,j], c1[i,j], c0[i+1,j], c0[i,j+1], c0[i+1,j+1])
//   out1[i,j] = max(c1[i,j], c0[i+1,j+1], c1[i+1,j], c1[i,j+1], c1[i+1,j+1])
// [B=4, C=32, H=512, W=512] f32 per coset; output [2,B,C,H,W].
// DRAM-bound at the ~537 MB traffic floor; measured ceiling ~6.46 TB/s.
// R9 = 2 output rows per thread (shares middle input row => 25% fewer load
// instructions) + PLAIN stores (R8 showed __stcs costs ~2us) + shuffle shifts.

#define QP_W 512
#define QP_VPR 128            // vec4 slots per row
#define QP_THREADS 256

__device__ __forceinline__ float qp_max5(float a, float b, float c, float d, float e) {
    return fmaxf(fmaxf(fmaxf(a, b), fmaxf(c, d)), e);
}

__global__ __launch_bounds__(QP_THREADS)
void LatticeMaxPooling_pair_kernel(
    const float* __restrict__ c0,
    const float* __restrict__ c1,
    float* __restrict__ out,
    int n_pairs,      // row pairs = B*C*H/2
    int H,            // rows per image (power of two, even)
    int total)        // elements per coset (fits int32)
{
    const float NEGINF = -INFINITY;
    const int n_work = n_pairs * QP_VPR;
    const int stride = gridDim.x * blockDim.x;
    const int hmask = H - 1;
    const bool last_lane = ((threadIdx.x & 31) == 31);

    for (int idx = blockIdx.x * blockDim.x + threadIdx.x; idx < n_work; idx += stride) {
        const int p     = idx >> 7;               // row-pair index
        const int t     = idx & (QP_VPR - 1);
        const int r0    = p * 2;                  // first output row (even)
        const int i0    = r0 & hmask;             // i0 even => i0+1 < H always
        const int base0 = r0 * QP_W;
        const bool has2 = (i0 + 2 < H);           // row r0+2 within image?
        const bool has_e = (t != QP_VPR - 1);

        // 6 vec4 loads: rows r0, r0+1, r0+2 of both cosets (middle row shared).
        float4 a0 = reinterpret_cast<const float4*>(c0 + base0)[t];
        float4 b0 = reinterpret_cast<const float4*>(c1 + base0)[t];
        float4 a1 = reinterpret_cast<const float4*>(c0 + base0 + QP_W)[t];
        float4 b1 = reinterpret_cast<const float4*>(c1 + base0 + QP_W)[t];
        float4 a2, b2;
        if (has2) {
            a2 = reinterpret_cast<const float4*>(c0 + base0 + 2 * QP_W)[t];
            b2 = reinterpret_cast<const float4*>(c1 + base0 + 2 * QP_W)[t];
        } else {
            a2 = make_float4(NEGINF, NEGINF, NEGINF, NEGINF);
            b2 = a2;
        }

        // Warp-boundary tail (j0+4): lane 31 loads, others shuffle from lane+1.
        float a0e_l = NEGINF, b0e_l = NEGINF, a1e_l = NEGINF,
              b1e_l = NEGINF, a2e_l = NEGINF, b2e_l = NEGINF;
        if (last_lane && has_e) {
            const int e = base0 + t * 4 + 4;
            a0e_l = c0[e];
            b0e_l = c1[e];
            a1e_l = c0[e + QP_W];
            b1e_l = c1[e + QP_W];
            if (has2) {
                a2e_l = c0[e + 2 * QP_W];
                b2e_l = c1[e + 2 * QP_W];
            }
        }
        float a0e = __shfl_down_sync(0xFFFFFFFFu, a0.x, 1);
        float b0e = __shfl_down_sync(0xFFFFFFFFu, b0.x, 1);
        float a1e = __shfl_down_sync(0xFFFFFFFFu, a1.x, 1);
        float b1e = __shfl_down_sync(0xFFFFFFFFu, b1.x, 1);
        float a2e = __shfl_down_sync(0xFFFFFFFFu, a2.x, 1);
        float b2e = __shfl_down_sync(0xFFFFFFFFu, b2.x, 1);
        if (last_lane) {
            a0e = a0e_l; b0e = b0e_l; a1e = a1e_l;
            b1e = b1e_l; a2e = a2e_l; b2e = b2e_l;
        }

        // j+1 shifted views
        const float4 sa0 = make_float4(a0.y, a0.z, a0.w, a0e);
        const float4 sa1 = make_float4(a1.y, a1.z, a1.w, a1e);
        const float4 sa2 = make_float4(a2.y, a2.z, a2.w, a2e);
        const float4 sb0 = make_float4(b0.y, b0.z, b0.w, b0e);
        const float4 sb1 = make_float4(b1.y, b1.z, b1.w, b1e);
        const float4 sb2 = make_float4(b2.y, b2.z, b2.w, b2e);

        float4 o00, o10, o01, o11;
        // Row r0
        o00.x = qp_max5(a0.x, b0.x, a1.x, sa0.x, sa1.x);
        o00.y = qp_max5(a0.y, b0.y, a1.y, sa0.y, sa1.y);
        o00.z = qp_max5(a0.z, b0.z, a1.z, sa0.z, sa1.z);
        o00.w = qp_max5(a0.w, b0.w, a1.w, sa0.w, sa1.w);
        o10.x = qp_max5(b0.x, sa1.x, b1.x, sb0.x, sb1.x);
        o10.y = qp_max5(b0.y, sa1.y, b1.y, sb0.y, sb1.y);
        o10.z = qp_max5(b0.z, sa1.z, b1.z, sb0.z, sb1.z);
        o10.w = qp_max5(b0.w, sa1.w, b1.w, sb0.w, sb1.w);
        // Row r0+1
        o01.x = qp_max5(a1.x, b1.x, a2.x, sa1.x, sa2.x);
        o01.y = qp_max5(a1.y, b1.y, a2.y, sa1.y, sa2.y);
        o01.z = qp_max5(a1.z, b1.z, a2.z, sa1.z, sa2.z);
        o01.w = qp_max5(a1.w, b1.w, a2.w, sa1.w, sa2.w);
        o11.x = qp_max5(b1.x, sa2.x, b2.x, sb1.x, sb2.x);
        o11.y = qp_max5(b1.y, sa2.y, b2.y, sb1.y, sb2.y);
        o11.z = qp_max5(b1.z, sa2.z, b2.z, sb1.z, sb2.z);
        o11.w = qp_max5(b1.w, sa2.w, b2.w, sb1.w, sb2.w);

        // Plain stores (R8 isolated __stcs as a ~2us regression).
        reinterpret_cast<float4*>(out + base0)[t]                 = o00;
        reinterpret_cast<float4*>(out + base0 + QP_W)[t]          = o01;
        reinterpret_cast<float4*>(out + total + base0)[t]         = o10;
        reinterpret_cast<float4*>(out + total + base0 + QP_W)[t]  = o11;
    }
}

// Fallback (unaligned pointers / odd sizes): scalar path. Not expected to run.
__global__ __launch_bounds__(QP_THREADS)
void LatticeMaxPooling_scalar_kernel(
    const float* __restrict__ c0,
    const float* __restrict__ c1,
    float* __restrict__ out,
    long long n_rows, int H, long long total)
{
    const float NEGINF = -INFINITY;
    const long long n_work = n_rows * QP_W;
    const long long stride = (long long)gridDim.x * blockDim.x;
    for (long long idx = (long long)blockIdx.x * blockDim.x + threadIdx.x;
         idx < n_work; idx += stride) {
        const long long row = idx / QP_W;
        const int j = (int)(idx - row * QP_W);
        const int i = (int)(row % H);
        const long long base = row * QP_W;
        const bool he = (j + 1 < QP_W);
        const bool hn = (i + 1 < H);

        float a00 = c0[base + j];
        float b00 = c1[base + j];
        float a01 = he ? c0[base + j + 1] : NEGINF;
        float b01 = he ? c1[base + j + 1] : NEGINF;
        float a10 = hn ? c0[base + QP_W + j] : NEGINF;
        float b10 = hn ? c1[base + QP_W + j] : NEGINF;
        float a11 = (hn && he) ? c0[base + QP_W + j + 1] : NEGINF;
        float b11 = (hn && he) ? c1[base + QP_W + j + 1] : NEGINF;

        out[base + j]         = qp_max5(a00, b00, a10, a01, a11);
        out[total + base + j] = qp_max5(b00, a11, b10, b01, b11);
    }
}

extern "C" void kernel_launch(void* const* d_in, const int* in_sizes, int n_in,
                              void* d_out, int out_size) {
    const float* c0 = (const float*)d_in[0];
    const float* c1 = (const float*)d_in[1];
    float* out = (float*)d_out;

    long long t_in  = (long long)in_sizes[0];
    long long t_out = (long long)out_size / 2;
    long long total = (t_in < t_out) ? t_in : t_out;

    const int H = 512;
    const long long n_rows = total / QP_W;
    total = n_rows * QP_W;

    const bool fast =
        ((uintptr_t)c0 % 16 == 0) && ((uintptr_t)c1 % 16 == 0) &&
        ((uintptr_t)out % 16 == 0) &&
        ((n_rows % 2) == 0) &&
        (2 * total < 0x7FFFFFFFLL);           // int32-indexable

    if (fast) {
        const int n_pairs = (int)(n_rows / 2);
        const int n_work = n_pairs * QP_VPR;
        int blocks = (n_work + QP_THREADS - 1) / QP_THREADS;
        if (blocks < 1) blocks = 1;
        LatticeMaxPooling_pair_kernel<<<blocks, QP_THREADS>>>(
            c0, c1, out, n_pairs, H, (int)total);
    } else {
        const long long n_work = n_rows * QP_W;
        int blocks = (int)((n_work + QP_THREADS - 1) / QP_THREADS);
        if (blocks < 1) blocks = 1;
        LatticeMaxPooling_scalar_kernel<<<blocks, QP_THREADS>>>(
            c0, c1, out, n_rows, H, total);
    }
}